// round 1
// baseline (speedup 1.0000x reference)
#include <cuda_runtime.h>

#define B_  32
#define C_  64
#define H_  128
#define W_  128
#define HW  16384            // H_*W_
#define CR  38               // floor(0.6*64)=38, even -> C_r=38
#define CIR 26               // 64-38

// Scratch (allocation-free rule: __device__ globals)
__device__ unsigned long long g_mask[B_];
__device__ float g_ravg [B_ * HW];
__device__ float g_rmax [B_ * HW];
__device__ float g_iravg[B_ * HW];
__device__ float g_irmax[B_ * HW];
__device__ float g_A1   [B_ * HW];
__device__ float g_A2   [B_ * HW];

// ---------------------------------------------------------------------------
// Kernel 1: per-batch relevance bitmask from top-k(CR) of M[b, :]
// rank(c) = #{j : M[j] > M[c]} + #{j < c : M[j] == M[c]}  (jax top_k tiebreak)
// ---------------------------------------------------------------------------
__global__ void mask_kernel(const float* __restrict__ M) {
    int b = blockIdx.x;
    int c = threadIdx.x;
    __shared__ float m[C_];
    __shared__ unsigned long long sm;
    if (c == 0) sm = 0ull;
    m[c] = M[b * C_ + c];
    __syncthreads();
    float v = m[c];
    int rank = 0;
    #pragma unroll
    for (int j = 0; j < C_; j++) {
        float mj = m[j];
        rank += (mj > v) || (mj == v && j < c);
    }
    if (rank < CR) atomicOr(&sm, 1ull << c);
    __syncthreads();
    if (c == 0) g_mask[b] = sm;
}

// ---------------------------------------------------------------------------
// Kernel 2: channel reductions per pixel.
// relevant = mask*x has exact zeros on masked-out channels, so the channel
// max ALWAYS includes 0 -> init max accumulators to 0.
// ---------------------------------------------------------------------------
__global__ void reduce_kernel(const float* __restrict__ x) {
    int p = blockIdx.x * blockDim.x + threadIdx.x;   // 0 .. B_*HW-1
    int b   = p >> 14;
    int pix = p & (HW - 1);
    unsigned long long mask = g_mask[b];
    const float* xb = x + (size_t)b * C_ * HW + pix;

    float rsum = 0.f, rmax = 0.f, irsum = 0.f, irmax = 0.f;
    #pragma unroll 16
    for (int c = 0; c < C_; c++) {
        float v = __ldg(xb + (size_t)c * HW);
        bool rel = (mask >> c) & 1ull;
        if (rel) { rsum  += v; rmax  = fmaxf(rmax,  v); }
        else     { irsum += v; irmax = fmaxf(irmax, v); }
    }
    // mean over C then * C/C_r  == sum / C_r
    g_ravg [p] = rsum  * (1.0f / (float)CR);
    g_rmax [p] = rmax;
    g_iravg[p] = irsum * (1.0f / (float)CIR);
    g_irmax[p] = irmax;
}

// ---------------------------------------------------------------------------
// Kernel 3: 7x7 cross-correlation (2 in-ch -> 1 out-ch), zero pad 3,
// then BN (inference) + relu + sigmoid. Computes A_S1 and A_S2 together.
// ---------------------------------------------------------------------------
__global__ void conv_kernel(const float* __restrict__ cw,
                            const float* __restrict__ gamma,
                            const float* __restrict__ beta,
                            const float* __restrict__ mean,
                            const float* __restrict__ var) {
    __shared__ float sw[98];
    if (threadIdx.x < 98) sw[threadIdx.x] = cw[threadIdx.x];
    __syncthreads();

    int p = blockIdx.x * blockDim.x + threadIdx.x;
    int b   = p >> 14;
    int pix = p & (HW - 1);
    int h = pix >> 7;
    int w = pix & (W_ - 1);

    const float* ra = g_ravg  + b * HW;
    const float* rm = g_rmax  + b * HW;
    const float* ia = g_iravg + b * HW;
    const float* im = g_irmax + b * HW;

    float y1 = 0.f, y2 = 0.f;
    #pragma unroll
    for (int kh = 0; kh < 7; kh++) {
        int hh = h + kh - 3;
        if (hh < 0 || hh >= H_) continue;
        #pragma unroll
        for (int kw = 0; kw < 7; kw++) {
            int ww = w + kw - 3;
            if (ww < 0 || ww >= W_) continue;
            int q = hh * W_ + ww;
            float w0 = sw[kh * 7 + kw];        // conv_w[0,0,kh,kw] -> avg channel
            float w1 = sw[49 + kh * 7 + kw];   // conv_w[0,1,kh,kw] -> max channel
            y1 = fmaf(ra[q], w0, fmaf(rm[q], w1, y1));
            y2 = fmaf(ia[q], w0, fmaf(im[q], w1, y2));
        }
    }

    float scale = rsqrtf(var[0] + 1e-5f) * gamma[0];
    float bias  = beta[0] - mean[0] * scale;
    y1 = fmaf(y1, scale, bias);
    y2 = fmaf(y2, scale, bias);
    y1 = fmaxf(y1, 0.f);
    y2 = fmaxf(y2, 0.f);
    g_A1[p] = 1.0f / (1.0f + expf(-y1));
    g_A2[p] = 1.0f / (1.0f + expf(-y2));
}

// ---------------------------------------------------------------------------
// Kernel 4: out = x * (relevant-channel ? A_S1 : A_S2), float4-vectorized.
// ---------------------------------------------------------------------------
__global__ void combine_kernel(const float* __restrict__ x,
                               float* __restrict__ out) {
    size_t i = (size_t)blockIdx.x * blockDim.x + threadIdx.x;  // float4 index
    size_t e = i << 2;                                         // element index
    int b    = (int)(e >> 20);          // C_*HW = 2^20
    int c    = (int)((e >> 14) & 63);
    int pix4 = (int)((e & (HW - 1)) >> 2);

    const float4* x4 = (const float4*)x;
    float4 v = x4[i];

    bool rel = (g_mask[b] >> c) & 1ull;
    const float4* A4 = (const float4*)(rel ? g_A1 : g_A2);
    float4 a = A4[((size_t)b * HW >> 2) + pix4];

    float4 r;
    r.x = v.x * a.x;
    r.y = v.y * a.y;
    r.z = v.z * a.z;
    r.w = v.w * a.w;
    ((float4*)out)[i] = r;
}

// ---------------------------------------------------------------------------
extern "C" void kernel_launch(void* const* d_in, const int* in_sizes, int n_in,
                              void* d_out, int out_size) {
    const float* x     = (const float*)d_in[0];
    const float* M     = (const float*)d_in[1];
    const float* cw    = (const float*)d_in[2];
    const float* gamma = (const float*)d_in[3];
    const float* beta  = (const float*)d_in[4];
    const float* mean  = (const float*)d_in[5];
    const float* var   = (const float*)d_in[6];
    float* out = (float*)d_out;

    mask_kernel<<<B_, C_>>>(M);

    const int NPIX = B_ * HW;                 // 524288
    reduce_kernel<<<NPIX / 256, 256>>>(x);

    conv_kernel<<<NPIX / 256, 256>>>(cw, gamma, beta, mean, var);

    const int NV4 = (B_ * C_ * HW) / 4;       // 8388608
    combine_kernel<<<NV4 / 256, 256>>>(x, out);
}